// round 2
// baseline (speedup 1.0000x reference)
#include <cuda_runtime.h>
#include <cstdint>

// BaseVectorQuantizer: N=131072 vectors (D=64) vs K=1024 codes.
// dist_k = fp32( fp32(||x||^2 + ||e_k||^2) - 2*dot(x,e_k) )   (replicates JAX fp32 rounding)
// out[b,d,h,w] = x + (codebook[argmin_k dist_k][d] - x)       (fp32 STE)

#define NUM_K 1024
#define DIM   64
#define CHUNK 128          // codes staged in smem per iteration
#define TPB   128
#define HW    4096         // 64*64
#define NVEC  131072       // 32*4096

__device__ float g_esq[NUM_K];

__global__ void esq_kernel(const float* __restrict__ cb) {
    int k = blockIdx.x * blockDim.x + threadIdx.x;
    if (k < NUM_K) {
        float s = 0.f;
        #pragma unroll
        for (int i = 0; i < DIM; i++) {
            float v = cb[k * DIM + i];
            s = __fadd_rn(s, __fmul_rn(v, v));   // mul-then-add, no contraction
        }
        g_esq[k] = s;
    }
}

__global__ __launch_bounds__(TPB) void vq_kernel(const float* __restrict__ x_in,
                                                 const float* __restrict__ cb,
                                                 float* __restrict__ out) {
    // smem chunk layout: se[i * CHUNK + kl] = codebook[c*CHUNK + kl][i]
    // -> 4 consecutive codes at one dim i are 16B-contiguous (one 16B broadcast LDS).
    __shared__ float se[DIM * CHUNK];     // 32 KB
    __shared__ float sesq[CHUNK];

    const int n = blockIdx.x * TPB + threadIdx.x;     // vector id
    const int b = n >> 12;                            // batch
    const int s = n & (HW - 1);                       // h*64+w
    const float* xp = x_in + (size_t)b * (DIM * HW) + s;

    // x duplicated into packed f32x2 (x_i, x_i) for fma.rn.f32x2; also ||x||^2 in fp32
    unsigned long long xdup[DIM];
    float xsq = 0.f;
    #pragma unroll
    for (int i = 0; i < DIM; i++) {
        float v = xp[i * HW];
        xsq = __fadd_rn(xsq, __fmul_rn(v, v));
        asm("mov.b64 %0, {%1, %1};" : "=l"(xdup[i]) : "f"(v));
    }

    uint32_t se_base;
    asm("{ .reg .u64 t; cvta.to.shared.u64 t, %1; cvt.u32.u64 %0, t; }"
        : "=r"(se_base) : "l"(se));

    float best  = 3.4e38f;
    int   bestk = 0;

    for (int c = 0; c < NUM_K / CHUNK; c++) {
        __syncthreads();
        // stage chunk transposed: coalesced 16B global reads, conflict-free smem writes
        const float* cbc = cb + c * CHUNK * DIM;
        #pragma unroll 1
        for (int idx = threadIdx.x; idx < CHUNK * (DIM / 4); idx += TPB) {
            int i4 = idx & (DIM / 4 - 1);
            int kl = idx >> 4;
            float4 v = *reinterpret_cast<const float4*>(cbc + kl * DIM + i4 * 4);
            se[(i4 * 4 + 0) * CHUNK + kl] = v.x;
            se[(i4 * 4 + 1) * CHUNK + kl] = v.y;
            se[(i4 * 4 + 2) * CHUNK + kl] = v.z;
            se[(i4 * 4 + 3) * CHUNK + kl] = v.w;
        }
        sesq[threadIdx.x] = g_esq[c * CHUNK + threadIdx.x];
        __syncthreads();

        #pragma unroll 1
        for (int q = 0; q < CHUNK / 4; q++) {
            unsigned long long a01 = 0ull, a23 = 0ull;   // packed fp32 dot accumulators
            uint32_t addr = se_base + q * 16;
            #pragma unroll
            for (int i = 0; i < DIM; i++) {
                unsigned long long e01, e23;
                asm("ld.shared.v2.u64 {%0, %1}, [%2];"
                    : "=l"(e01), "=l"(e23)
                    : "r"(addr + i * (CHUNK * 4)));
                asm("fma.rn.f32x2 %0, %1, %2, %0;" : "+l"(a01) : "l"(xdup[i]), "l"(e01));
                asm("fma.rn.f32x2 %0, %1, %2, %0;" : "+l"(a23) : "l"(xdup[i]), "l"(e23));
            }
            float d0, d1, d2, d3;
            asm("mov.b64 {%0, %1}, %2;" : "=f"(d0), "=f"(d1) : "l"(a01));
            asm("mov.b64 {%0, %1}, %2;" : "=f"(d2), "=f"(d3) : "l"(a23));
            const int kb = c * CHUNK + q * 4;
            // dist = round( round(xsq + esq_k) - 2*dot )   [2*dot exact]
            float t0 = __fadd_rn(xsq, sesq[q * 4 + 0]);
            float t1 = __fadd_rn(xsq, sesq[q * 4 + 1]);
            float t2 = __fadd_rn(xsq, sesq[q * 4 + 2]);
            float t3 = __fadd_rn(xsq, sesq[q * 4 + 3]);
            float s0 = __fsub_rn(t0, __fadd_rn(d0, d0));
            float s1 = __fsub_rn(t1, __fadd_rn(d1, d1));
            float s2 = __fsub_rn(t2, __fadd_rn(d2, d2));
            float s3 = __fsub_rn(t3, __fadd_rn(d3, d3));
            // strict < in ascending order == jnp.argmin first-min tie-break
            if (s0 < best) { best = s0; bestk = kb + 0; }
            if (s1 < best) { best = s1; bestk = kb + 1; }
            if (s2 < best) { best = s2; bestk = kb + 2; }
            if (s3 < best) { best = s3; bestk = kb + 3; }
        }
    }

    // gather winning code, apply fp32 straight-through (x + (q - x)), scatter BCHW
    const float4* brow = reinterpret_cast<const float4*>(cb + (size_t)bestk * DIM);
    float* op = out + (size_t)b * (DIM * HW) + s;
    #pragma unroll
    for (int j = 0; j < DIM / 4; j++) {
        float4 qv = __ldg(&brow[j]);
        float x0 = __int_as_float((int)(unsigned int)(xdup[j * 4 + 0] & 0xffffffffull));
        float x1 = __int_as_float((int)(unsigned int)(xdup[j * 4 + 1] & 0xffffffffull));
        float x2 = __int_as_float((int)(unsigned int)(xdup[j * 4 + 2] & 0xffffffffull));
        float x3 = __int_as_float((int)(unsigned int)(xdup[j * 4 + 3] & 0xffffffffull));
        op[(j * 4 + 0) * HW] = __fadd_rn(x0, __fsub_rn(qv.x, x0));
        op[(j * 4 + 1) * HW] = __fadd_rn(x1, __fsub_rn(qv.y, x1));
        op[(j * 4 + 2) * HW] = __fadd_rn(x2, __fsub_rn(qv.z, x2));
        op[(j * 4 + 3) * HW] = __fadd_rn(x3, __fsub_rn(qv.w, x3));
    }
}

extern "C" void kernel_launch(void* const* d_in, const int* in_sizes, int n_in,
                              void* d_out, int out_size) {
    const float* x  = (const float*)d_in[0];
    const float* cb = (const float*)d_in[1];
    // defensive: inputs = 8388608 elems, codebook = 65536 elems
    if (n_in >= 2 && in_sizes[0] == NUM_K * DIM && in_sizes[1] == NVEC * DIM) {
        const float* t = x; x = cb; cb = t;
    }
    float* out = (float*)d_out;

    esq_kernel<<<(NUM_K + 127) / 128, 128>>>(cb);
    vq_kernel<<<NVEC / TPB, TPB>>>(x, cb, out);
}

// round 3
// speedup vs baseline: 1.6848x; 1.6848x over previous
#include <cuda_runtime.h>
#include <cstdint>

// BaseVectorQuantizer: N=131072 vectors (D=64) vs K=1024 codes.
// dist_k = fp32( fp32(||x||^2 + ||e_k||^2) - 2*dot(x,e_k) )
// out[b,d,h,w] = x + (codebook[argmin_k dist_k][d] - x)   (fp32 STE)
//
// V=2 vectors/thread, x held as natural (x_2p, x_2p+1) f32x2 pairs (no dup).
// Codebook row-major in smem; each broadcast LDS.128 (1 code, 4 dims) feeds
// 4 fma.rn.f32x2 -> shared-pipe traffic halved vs transposed layout.

#define NUM_K 1024
#define DIM   64
#define CHUNK 128
#define TPB   128
#define HW    4096
#define NVEC  131072
#define VPB   256            // vectors per CTA (V=2 * TPB)

__device__ float g_esq[NUM_K];

__global__ void esq_kernel(const float* __restrict__ cb) {
    int k = blockIdx.x * blockDim.x + threadIdx.x;
    if (k < NUM_K) {
        float s = 0.f;
        #pragma unroll
        for (int i = 0; i < DIM; i++) {
            float v = cb[k * DIM + i];
            s = __fadd_rn(s, __fmul_rn(v, v));
        }
        g_esq[k] = s;
    }
}

__global__ __launch_bounds__(TPB, 3) void vq_kernel(const float* __restrict__ x_in,
                                                    const float* __restrict__ cb,
                                                    float* __restrict__ out) {
    __shared__ __align__(16) float se[CHUNK * DIM];   // row-major: se[k*64 + d], 32 KB
    __shared__ float sesq[CHUNK];

    const int t    = threadIdx.x;
    const int base = blockIdx.x * VPB;
    const int b    = base >> 12;
    const int sA   = (base & (HW - 1)) + t;           // vector A spatial index
    const float* xpA = x_in + (size_t)b * (DIM * HW) + sA;
    const float* xpB = xpA + TPB;                     // vector B = A + 128

    // Load x for both vectors as packed f32x2 dim-pairs; accumulate ||x||^2
    // in reference-like sequential-dim order.
    unsigned long long xA2[DIM / 2], xB2[DIM / 2];
    float xsqA = 0.f, xsqB = 0.f;
    #pragma unroll
    for (int p = 0; p < DIM / 2; p++) {
        float a0 = xpA[(2 * p) * HW], a1 = xpA[(2 * p + 1) * HW];
        float c0 = xpB[(2 * p) * HW], c1 = xpB[(2 * p + 1) * HW];
        xsqA = __fadd_rn(xsqA, __fmul_rn(a0, a0));
        xsqA = __fadd_rn(xsqA, __fmul_rn(a1, a1));
        xsqB = __fadd_rn(xsqB, __fmul_rn(c0, c0));
        xsqB = __fadd_rn(xsqB, __fmul_rn(c1, c1));
        asm("mov.b64 %0, {%1, %2};" : "=l"(xA2[p]) : "f"(a0), "f"(a1));
        asm("mov.b64 %0, {%1, %2};" : "=l"(xB2[p]) : "f"(c0), "f"(c1));
    }

    uint32_t se_base;
    asm("{ .reg .u64 t; cvta.to.shared.u64 t, %1; cvt.u32.u64 %0, t; }"
        : "=r"(se_base) : "l"(se));

    float bestA = 3.4e38f, bestB = 3.4e38f;
    int   bkA = 0, bkB = 0;

    for (int c = 0; c < NUM_K / CHUNK; c++) {
        __syncthreads();
        // straight coalesced copy: conflict-free 16B stores
        const float4* src = reinterpret_cast<const float4*>(cb + c * CHUNK * DIM);
        float4* dst = reinterpret_cast<float4*>(se);
        #pragma unroll
        for (int j = 0; j < (CHUNK * DIM / 4) / TPB; j++)
            dst[j * TPB + t] = src[j * TPB + t];
        sesq[t] = g_esq[c * CHUNK + t];
        __syncthreads();

        #pragma unroll 1
        for (int k = 0; k < CHUNK; k++) {
            unsigned long long a0 = 0ull, a1 = 0ull, b0 = 0ull, b1 = 0ull;
            const uint32_t addr = se_base + k * (DIM * 4);
            #pragma unroll
            for (int d4 = 0; d4 < DIM / 4; d4++) {
                unsigned long long e0, e1;   // (e_{4d4},e_{4d4+1}), (e_{4d4+2},e_{4d4+3})
                asm("ld.shared.v2.u64 {%0, %1}, [%2];"
                    : "=l"(e0), "=l"(e1) : "r"(addr + d4 * 16));
                asm("fma.rn.f32x2 %0, %1, %2, %0;" : "+l"(a0) : "l"(xA2[2 * d4]),     "l"(e0));
                asm("fma.rn.f32x2 %0, %1, %2, %0;" : "+l"(a1) : "l"(xA2[2 * d4 + 1]), "l"(e1));
                asm("fma.rn.f32x2 %0, %1, %2, %0;" : "+l"(b0) : "l"(xB2[2 * d4]),     "l"(e0));
                asm("fma.rn.f32x2 %0, %1, %2, %0;" : "+l"(b1) : "l"(xB2[2 * d4 + 1]), "l"(e1));
            }
            unsigned long long sa, sb;
            asm("add.rn.f32x2 %0, %1, %2;" : "=l"(sa) : "l"(a0), "l"(a1));
            asm("add.rn.f32x2 %0, %1, %2;" : "=l"(sb) : "l"(b0), "l"(b1));
            float alo, ahi, blo, bhi;
            asm("mov.b64 {%0, %1}, %2;" : "=f"(alo), "=f"(ahi) : "l"(sa));
            asm("mov.b64 {%0, %1}, %2;" : "=f"(blo), "=f"(bhi) : "l"(sb));
            float dA = __fadd_rn(alo, ahi);
            float dB = __fadd_rn(blo, bhi);
            float esq = sesq[k];
            // dist = round( round(xsq + esq) - 2*dot )   [2*dot exact]
            float distA = __fsub_rn(__fadd_rn(xsqA, esq), __fadd_rn(dA, dA));
            float distB = __fsub_rn(__fadd_rn(xsqB, esq), __fadd_rn(dB, dB));
            int kk = c * CHUNK + k;
            if (distA < bestA) { bestA = distA; bkA = kk; }
            if (distB < bestB) { bestB = distB; bkB = kk; }
        }
    }

    // gather winning codes, fp32 straight-through, scatter BCHW
    const float4* rowA = reinterpret_cast<const float4*>(cb + (size_t)bkA * DIM);
    const float4* rowB = reinterpret_cast<const float4*>(cb + (size_t)bkB * DIM);
    float* opA = out + (size_t)b * (DIM * HW) + sA;
    float* opB = opA + TPB;
    #pragma unroll
    for (int j = 0; j < DIM / 4; j++) {
        float4 qA = __ldg(&rowA[j]);
        float4 qB = __ldg(&rowB[j]);
        float a0, a1, a2, a3, c0, c1, c2, c3;
        asm("mov.b64 {%0, %1}, %2;" : "=f"(a0), "=f"(a1) : "l"(xA2[2 * j]));
        asm("mov.b64 {%0, %1}, %2;" : "=f"(a2), "=f"(a3) : "l"(xA2[2 * j + 1]));
        asm("mov.b64 {%0, %1}, %2;" : "=f"(c0), "=f"(c1) : "l"(xB2[2 * j]));
        asm("mov.b64 {%0, %1}, %2;" : "=f"(c2), "=f"(c3) : "l"(xB2[2 * j + 1]));
        opA[(4 * j + 0) * HW] = __fadd_rn(a0, __fsub_rn(qA.x, a0));
        opA[(4 * j + 1) * HW] = __fadd_rn(a1, __fsub_rn(qA.y, a1));
        opA[(4 * j + 2) * HW] = __fadd_rn(a2, __fsub_rn(qA.z, a2));
        opA[(4 * j + 3) * HW] = __fadd_rn(a3, __fsub_rn(qA.w, a3));
        opB[(4 * j + 0) * HW] = __fadd_rn(c0, __fsub_rn(qB.x, c0));
        opB[(4 * j + 1) * HW] = __fadd_rn(c1, __fsub_rn(qB.y, c1));
        opB[(4 * j + 2) * HW] = __fadd_rn(c2, __fsub_rn(qB.z, c2));
        opB[(4 * j + 3) * HW] = __fadd_rn(c3, __fsub_rn(qB.w, c3));
    }
}

extern "C" void kernel_launch(void* const* d_in, const int* in_sizes, int n_in,
                              void* d_out, int out_size) {
    const float* x  = (const float*)d_in[0];
    const float* cb = (const float*)d_in[1];
    if (n_in >= 2 && in_sizes[0] == NUM_K * DIM && in_sizes[1] == NVEC * DIM) {
        const float* t = x; x = cb; cb = t;
    }
    float* out = (float*)d_out;

    esq_kernel<<<(NUM_K + 127) / 128, 128>>>(cb);
    vq_kernel<<<NVEC / VPB, TPB>>>(x, cb, out);
}